// round 1
// baseline (speedup 1.0000x reference)
#include <cuda_runtime.h>
#include <math.h>

// Problem constants
#define NGRAPHS 2048
#define NPG     32      // nodes per graph
#define EPG     256     // edges per graph
#define INDIM   128
#define HOUT    256     // heads(4) * D(64)
#define HSR     258     // padded row stride for hs/hd (bank-conflict reduction)

// ---------------- packed f32x2 FMA ----------------
__device__ __forceinline__ float2 ffma2(float2 a, float2 b, float2 c) {
    float2 d;
    asm("fma.rn.f32x2 %0, %1, %2, %3;"
        : "=l"(*(unsigned long long*)&d)
        : "l"(*(unsigned long long*)&a),
          "l"(*(unsigned long long*)&b),
          "l"(*(unsigned long long*)&c));
    return d;
}

// ---------------- SMEM layout (floats) ----------------
// hs   [32*HSR]            projected src features (padded stride)
// hd   [32*HSR]            projected dst features
// agg  [8192]              aggregation output [32][256]; doubles as xT [128][32] for layer-1 GEMM input
// hbuf [2048]              layer-1 pooled output (as [64][32] k-major) / layer-2 pooled output [32][64]
// elog [1024]              edge logits -> exp values  [256][4]
// avec [256]               attention vector a (h*64+d)
// invd [128]               1/denominator per (node, head)
// alphaS [32]              readout softmax weights
// then ints: esrc[256], edst[256], cnt[32], coff[33], fill[32], elist[256]
#define SMEM_FLOATS (32*HSR*2 + 8192 + 2048 + 1024 + 256 + 128 + 32)
#define SMEM_INTS   (256 + 256 + 32 + 33 + 32 + 256)
#define SMEM_BYTES  ((SMEM_FLOATS + SMEM_INTS) * 4)

// Dual GEMM: out_s = xT^T @ Ws + bs, out_d = xT^T @ Wd + bd
// xT is [K][32] k-major in SMEM. Each thread owns output column j = tid (0..255),
// computing all 32 nodes as 16 float2 accumulators per matrix.
template<int K>
__device__ __forceinline__ void gemm_dual(
    const float* __restrict__ Ws, const float* __restrict__ bsv,
    const float* __restrict__ Wd, const float* __restrict__ bdv,
    const float* xT, float* hs, float* hd, int j)
{
    float bs = __ldg(bsv + j), bd = __ldg(bdv + j);
    float2 aS[16], aD[16];
#pragma unroll
    for (int i = 0; i < 16; i++) { aS[i] = make_float2(bs, bs); aD[i] = make_float2(bd, bd); }
#pragma unroll 4
    for (int k = 0; k < K; k++) {
        float ws = __ldg(Ws + k * HOUT + j);
        float wd = __ldg(Wd + k * HOUT + j);
        float2 w2s = make_float2(ws, ws), w2d = make_float2(wd, wd);
        const float2* xr = (const float2*)(xT + k * 32);
#pragma unroll
        for (int i = 0; i < 16; i++) {
            float2 xv = xr[i];
            aS[i] = ffma2(xv, w2s, aS[i]);
            aD[i] = ffma2(xv, w2d, aD[i]);
        }
    }
#pragma unroll
    for (int i = 0; i < 16; i++) {
        hs[(2*i)*HSR + j]   = aS[i].x;
        hs[(2*i+1)*HSR + j] = aS[i].y;
        hd[(2*i)*HSR + j]   = aD[i].x;
        hd[(2*i+1)*HSR + j] = aD[i].y;
    }
}

// Edge logits for edge e (thread-private): e_logit[h] = a[h] . leaky_relu(hs[s] + hd[t])
__device__ __forceinline__ void edge_logits(
    const float* hs, const float* hd, const float* avec, float* elog,
    int e, int s, int t)
{
    const float2* ps = (const float2*)(hs + s * HSR);
    const float2* pd = (const float2*)(hd + t * HSR);
    const float2* pa = (const float2*)avec;
#pragma unroll
    for (int h = 0; h < 4; h++) {
        float accx = 0.f, accy = 0.f;
#pragma unroll 8
        for (int d2 = 0; d2 < 32; d2++) {
            float2 vs = ps[h*32 + d2];
            float2 vd = pd[h*32 + d2];
            float2 av = pa[h*32 + d2];
            float vx = vs.x + vd.x, vy = vs.y + vd.y;
            vx = vx > 0.f ? vx : 0.2f * vx;
            vy = vy > 0.f ? vy : 0.2f * vy;
            accx = fmaf(vx, av.x, accx);
            accy = fmaf(vy, av.y, accy);
        }
        elog[e*4 + h] = accx + accy;
    }
}

// Full attention stage: logits -> edge softmax (per dst,head, via CSR) -> aggregation
__device__ __forceinline__ void attention_block(
    const float* hs, const float* hd, const float* avec,
    float* elog, float* invd, float* agg,
    const int* esrc, const int* cnt, const int* coff, const int* elist,
    int s, int t, int tid)
{
    edge_logits(hs, hd, avec, elog, tid, s, t);
    __syncthreads();

    // softmax per (dst node, head): 128 workers
    if (tid < 128) {
        int n = tid >> 2, h = tid & 3;
        int b = coff[n], c = cnt[n];
        float m = -1e30f;
        for (int i = 0; i < c; i++) m = fmaxf(m, elog[elist[b+i]*4 + h]);
        float den = 0.f;
        for (int i = 0; i < c; i++) {
            int e = elist[b+i];
            float ex = expf(elog[e*4 + h] - m);
            elog[e*4 + h] = ex;
            den += ex;
        }
        invd[tid] = c ? (1.f / den) : 0.f;
    }
    __syncthreads();

    // aggregation: owner-computes. 32 nodes x 8 threads; each thread owns 32 dims.
    {
        int n = tid >> 3, c8 = tid & 7, h = c8 >> 1;
        int b = coff[n], c = cnt[n];
        float iv = invd[n*4 + h];
        float2 acc[16];
#pragma unroll
        for (int q = 0; q < 16; q++) acc[q] = make_float2(0.f, 0.f);
        for (int i = 0; i < c; i++) {
            int e  = elist[b+i];
            int s2 = esrc[e];
            float al = elog[e*4 + h] * iv;
            float2 a2 = make_float2(al, al);
            const float2* pr = (const float2*)(hs + s2*HSR + c8*32);
#pragma unroll
            for (int q = 0; q < 16; q++) acc[q] = ffma2(pr[q], a2, acc[q]);
        }
        float2* po = (float2*)(agg + n*HOUT + c8*32);
#pragma unroll
        for (int q = 0; q < 16; q++) po[q] = acc[q];
    }
    __syncthreads();
}

__global__ void __launch_bounds__(256)
gat_fused_kernel(const float* __restrict__ x,
                 const int* __restrict__ src, const int* __restrict__ dst,
                 const float* __restrict__ W1s, const float* __restrict__ b1s,
                 const float* __restrict__ W1d, const float* __restrict__ b1d,
                 const float* __restrict__ a1,
                 const float* __restrict__ W2s, const float* __restrict__ b2s,
                 const float* __restrict__ W2d, const float* __restrict__ b2d,
                 const float* __restrict__ a2,
                 const float* __restrict__ Wg, const float* __restrict__ bg,
                 float* __restrict__ out)
{
    extern __shared__ float smem[];
    float* hs     = smem;
    float* hd     = hs + 32*HSR;
    float* agg    = hd + 32*HSR;     // 8192 floats (also xT for layer 1)
    float* hbuf   = agg + 8192;      // 2048 floats
    float* elog   = hbuf + 2048;     // 1024
    float* avec   = elog + 1024;     // 256
    float* invd   = avec + 256;      // 128
    float* alphaS = invd + 128;      // 32
    int* esrc  = (int*)(alphaS + 32);
    int* edst  = esrc + EPG;
    int* cnt   = edst + EPG;
    int* coff  = cnt + 32;           // 33 entries
    int* fill  = coff + 33;
    int* elist = fill + 32;

    const int g = blockIdx.x;
    const int tid = threadIdx.x;

    // ---- load edges (local node ids) + degree count ----
    if (tid < 32) { cnt[tid] = 0; fill[tid] = 0; }
    __syncthreads();
    int myS, myT;
    {
        myS = src[g*EPG + tid] - g*NPG;
        myT = dst[g*EPG + tid] - g*NPG;
        esrc[tid] = myS;
        edst[tid] = myT;
        atomicAdd(&cnt[myT], 1);
    }
    // ---- load x transposed into agg region: xT[k][n], k<128 ----
    for (int i = tid; i < NPG*INDIM; i += 256) {
        int n = i >> 7, k = i & 127;
        agg[k*32 + n] = x[(g*NPG + n)*INDIM + k];
    }
    if (tid < 256) avec[tid] = a1[tid];
    __syncthreads();

    // ---- CSR prefix + scatter ----
    if (tid == 0) {
        int s = 0;
        for (int i = 0; i < 32; i++) { coff[i] = s; s += cnt[i]; }
        coff[32] = s;
    }
    __syncthreads();
    {
        int pos = coff[myT] + atomicAdd(&fill[myT], 1);
        elist[pos] = tid;
    }

    // ---- layer 1 GEMM: hs/hd = x @ W1s/W1d + b ----
    gemm_dual<INDIM>(W1s, b1s, W1d, b1d, agg, hs, hd, tid);
    __syncthreads();

    // ---- layer 1 attention ----
    attention_block(hs, hd, avec, elog, invd, agg, esrc, cnt, coff, elist, myS, myT, tid);

    // ---- head maxpool -> hbuf as [64][32] (k-major for layer-2 GEMM) ----
    for (int i = tid; i < NPG*64; i += 256) {
        int n = i >> 6, d = i & 63;
        const float* ar = agg + n*HOUT + d;
        float m = fmaxf(fmaxf(ar[0], ar[64]), fmaxf(ar[128], ar[192]));
        hbuf[d*32 + n] = m;
    }
    if (tid < 256) avec[tid] = a2[tid];
    __syncthreads();

    // ---- layer 2 GEMM: hs/hd = h1 @ W2s/W2d + b ----
    gemm_dual<64>(W2s, b2s, W2d, b2d, hbuf, hs, hd, tid);
    __syncthreads();

    // ---- layer 2 attention ----
    attention_block(hs, hd, avec, elog, invd, agg, esrc, cnt, coff, elist, myS, myT, tid);

    // ---- head maxpool -> hbuf as [32][64] row-major ----
    for (int i = tid; i < NPG*64; i += 256) {
        int n = i >> 6, d = i & 63;
        const float* ar = agg + n*HOUT + d;
        float m = fmaxf(fmaxf(ar[0], ar[64]), fmaxf(ar[128], ar[192]));
        hbuf[n*64 + d] = m;
    }
    __syncthreads();

    // ---- global attention pooling ----
    if (tid < 32) {
        int n = tid;
        float acc = __ldg(bg);
        const float* hr = hbuf + n*64;
#pragma unroll 8
        for (int d = 0; d < 64; d++) acc = fmaf(hr[d], __ldg(Wg + d), acc);
        // warp softmax over the 32 nodes
        float m = acc;
#pragma unroll
        for (int off = 16; off > 0; off >>= 1)
            m = fmaxf(m, __shfl_xor_sync(0xffffffffu, m, off));
        float ex = expf(acc - m);
        float den = ex;
#pragma unroll
        for (int off = 16; off > 0; off >>= 1)
            den += __shfl_xor_sync(0xffffffffu, den, off);
        alphaS[n] = ex / den;
    }
    __syncthreads();
    if (tid < 64) {
        int d = tid;
        float o = 0.f;
#pragma unroll 8
        for (int n = 0; n < 32; n++) o = fmaf(alphaS[n], hbuf[n*64 + d], o);
        out[g*64 + d] = o;
    }
}

extern "C" void kernel_launch(void* const* d_in, const int* in_sizes, int n_in,
                              void* d_out, int out_size) {
    const float* x   = (const float*)d_in[0];
    const int*   src = (const int*)d_in[1];
    const int*   dst = (const int*)d_in[2];
    // d_in[3] = graph_ids (unused; derivable from blockIdx)
    const float* W1s = (const float*)d_in[4];
    const float* b1s = (const float*)d_in[5];
    const float* W1d = (const float*)d_in[6];
    const float* b1d = (const float*)d_in[7];
    const float* a1  = (const float*)d_in[8];
    const float* W2s = (const float*)d_in[9];
    const float* b2s = (const float*)d_in[10];
    const float* W2d = (const float*)d_in[11];
    const float* b2d = (const float*)d_in[12];
    const float* a2  = (const float*)d_in[13];
    const float* Wg  = (const float*)d_in[14];
    const float* bg  = (const float*)d_in[15];
    float* out = (float*)d_out;

    cudaFuncSetAttribute(gat_fused_kernel,
                         cudaFuncAttributeMaxDynamicSharedMemorySize, SMEM_BYTES);
    gat_fused_kernel<<<NGRAPHS, 256, SMEM_BYTES>>>(
        x, src, dst, W1s, b1s, W1d, b1d, a1,
        W2s, b2s, W2d, b2d, a2, Wg, bg, out);
}

// round 2
// speedup vs baseline: 1.1517x; 1.1517x over previous
#include <cuda_runtime.h>
#include <math.h>

// Problem constants
#define NGRAPHS 2048
#define NPG     32      // nodes per graph
#define EPG     256     // edges per graph
#define INDIM   128
#define HOUT    256     // heads(4) * D(64)
#define HSR     258     // padded row stride for hs/hd (2-way max bank conflict)
#define NTHREADS 512

// ---------------- packed f32x2 FMA ----------------
__device__ __forceinline__ float2 ffma2(float2 a, float2 b, float2 c) {
    float2 d;
    asm("fma.rn.f32x2 %0, %1, %2, %3;"
        : "=l"(*(unsigned long long*)&d)
        : "l"(*(unsigned long long*)&a),
          "l"(*(unsigned long long*)&b),
          "l"(*(unsigned long long*)&c));
    return d;
}

// ---------------- SMEM layout (floats) ----------------
#define SMEM_FLOATS (32*HSR*2 + 8192 + 2048 + 1024 + 256 + 128 + 32)
#define SMEM_INTS   (256 + 256 + 32 + 33 + 32 + 256)
#define SMEM_BYTES  ((SMEM_FLOATS + SMEM_INTS) * 4)

// Dual GEMM with 512 threads, register blocking.
// tid decomposition: m = tid>>8 (0: src-proj, 1: dst-proj)
//                    cg = (tid>>2)&63 (column group: 4 cols j0=cg*4)
//                    ng = tid&3       (node group: 8 nodes ng*8..)
// Per k: 4 LDS.64 (x, shared across 8 column-groups in warp) + 1 LDG.128 (W) + 16 FFMA2.
template<int K>
__device__ __forceinline__ void gemm_dual(
    const float* __restrict__ Ws, const float* __restrict__ bsv,
    const float* __restrict__ Wd, const float* __restrict__ bdv,
    const float* xT, float* hs, float* hd, int tid)
{
    const int m  = tid >> 8;
    const int cg = (tid >> 2) & 63;
    const int ng = tid & 3;
    const float* W  = m ? Wd  : Ws;
    const float* bv = m ? bdv : bsv;
    float* out      = m ? hd  : hs;
    const int j0 = cg * 4;

    float2 acc[4][4];
#pragma unroll
    for (int c = 0; c < 4; c++) {
        float b = __ldg(bv + j0 + c);
#pragma unroll
        for (int i = 0; i < 4; i++) acc[c][i] = make_float2(b, b);
    }
    const float2* xbase = (const float2*)xT + ng * 4;
#pragma unroll 4
    for (int k = 0; k < K; k++) {
        float4 w = __ldg((const float4*)(W + k * HOUT) + cg);
        const float2* xr = xbase + k * 16;
        float2 x0 = xr[0], x1 = xr[1], x2 = xr[2], x3 = xr[3];
        float2 w0 = make_float2(w.x, w.x);
        float2 w1 = make_float2(w.y, w.y);
        float2 w2 = make_float2(w.z, w.z);
        float2 w3 = make_float2(w.w, w.w);
        acc[0][0] = ffma2(x0, w0, acc[0][0]);
        acc[0][1] = ffma2(x1, w0, acc[0][1]);
        acc[0][2] = ffma2(x2, w0, acc[0][2]);
        acc[0][3] = ffma2(x3, w0, acc[0][3]);
        acc[1][0] = ffma2(x0, w1, acc[1][0]);
        acc[1][1] = ffma2(x1, w1, acc[1][1]);
        acc[1][2] = ffma2(x2, w1, acc[1][2]);
        acc[1][3] = ffma2(x3, w1, acc[1][3]);
        acc[2][0] = ffma2(x0, w2, acc[2][0]);
        acc[2][1] = ffma2(x1, w2, acc[2][1]);
        acc[2][2] = ffma2(x2, w2, acc[2][2]);
        acc[2][3] = ffma2(x3, w2, acc[2][3]);
        acc[3][0] = ffma2(x0, w3, acc[3][0]);
        acc[3][1] = ffma2(x1, w3, acc[3][1]);
        acc[3][2] = ffma2(x2, w3, acc[3][2]);
        acc[3][3] = ffma2(x3, w3, acc[3][3]);
    }
#pragma unroll
    for (int c = 0; c < 4; c++)
#pragma unroll
        for (int i = 0; i < 4; i++) {
            out[(ng*8 + 2*i)  * HSR + j0 + c] = acc[c][i].x;
            out[(ng*8 + 2*i+1)* HSR + j0 + c] = acc[c][i].y;
        }
}

// Full attention stage: logits -> edge softmax (per dst,head, CSR) -> aggregation
__device__ __forceinline__ void attention_block(
    const float* hs, const float* hd, const float* avec,
    float* elog, float* invd, float* agg,
    const int* esrc, const int* edst, const int* cnt, const int* coff,
    const int* elist, int tid)
{
    // ---- edge logits: 512 threads = 256 edges x 2 head-pairs ----
    {
        int e  = tid & 255;
        int hp = tid >> 8;          // heads 2*hp, 2*hp+1
        int s = esrc[e], t = edst[e];
        const float2* ps = (const float2*)(hs + s * HSR);
        const float2* pd = (const float2*)(hd + t * HSR);
        const float2* pa = (const float2*)avec;
#pragma unroll
        for (int hh = 0; hh < 2; hh++) {
            int h = 2*hp + hh;
            float accx = 0.f, accy = 0.f;
#pragma unroll 8
            for (int d2 = 0; d2 < 32; d2++) {
                float2 vs = ps[h*32 + d2];
                float2 vd = pd[h*32 + d2];
                float2 av = pa[h*32 + d2];
                float vx = vs.x + vd.x, vy = vs.y + vd.y;
                vx = vx > 0.f ? vx : 0.2f * vx;
                vy = vy > 0.f ? vy : 0.2f * vy;
                accx = fmaf(vx, av.x, accx);
                accy = fmaf(vy, av.y, accy);
            }
            elog[e*4 + h] = accx + accy;
        }
    }
    __syncthreads();

    // ---- softmax per (dst node, head): 128 workers ----
    if (tid < 128) {
        int n = tid >> 2, h = tid & 3;
        int b = coff[n], c = cnt[n];
        float m = -1e30f;
        for (int i = 0; i < c; i++) m = fmaxf(m, elog[elist[b+i]*4 + h]);
        float den = 0.f;
        for (int i = 0; i < c; i++) {
            int e = elist[b+i];
            float ex = expf(elog[e*4 + h] - m);
            elog[e*4 + h] = ex;
            den += ex;
        }
        invd[tid] = c ? (1.f / den) : 0.f;
    }
    __syncthreads();

    // ---- aggregation: 32 nodes x 16 threads; each thread owns 16 dims ----
    {
        int n = tid >> 4, dg = tid & 15, h = dg >> 2;
        int b = coff[n], c = cnt[n];
        float iv = invd[n*4 + h];
        float2 acc[8];
#pragma unroll
        for (int q = 0; q < 8; q++) acc[q] = make_float2(0.f, 0.f);
        for (int i = 0; i < c; i++) {
            int e  = elist[b+i];
            int s2 = esrc[e];
            float al = elog[e*4 + h] * iv;
            float2 a2 = make_float2(al, al);
            const float2* pr = (const float2*)(hs + s2*HSR + dg*16);
#pragma unroll
            for (int q = 0; q < 8; q++) acc[q] = ffma2(pr[q], a2, acc[q]);
        }
        float2* po = (float2*)(agg + n*HOUT + dg*16);
#pragma unroll
        for (int q = 0; q < 8; q++) po[q] = acc[q];
    }
    __syncthreads();
}

__global__ void __launch_bounds__(NTHREADS, 1)
gat_fused_kernel(const float* __restrict__ x,
                 const int* __restrict__ src, const int* __restrict__ dst,
                 const float* __restrict__ W1s, const float* __restrict__ b1s,
                 const float* __restrict__ W1d, const float* __restrict__ b1d,
                 const float* __restrict__ a1,
                 const float* __restrict__ W2s, const float* __restrict__ b2s,
                 const float* __restrict__ W2d, const float* __restrict__ b2d,
                 const float* __restrict__ a2,
                 const float* __restrict__ Wg, const float* __restrict__ bg,
                 float* __restrict__ out)
{
    extern __shared__ float smem[];
    float* hs     = smem;
    float* hd     = hs + 32*HSR;
    float* agg    = hd + 32*HSR;     // 8192 floats (xT for layer 1; agg output)
    float* hbuf   = agg + 8192;      // 2048 floats
    float* elog   = hbuf + 2048;     // 1024
    float* avec   = elog + 1024;     // 256
    float* invd   = avec + 256;      // 128
    float* alphaS = invd + 128;      // 32
    int* esrc  = (int*)(alphaS + 32);
    int* edst  = esrc + EPG;
    int* cnt   = edst + EPG;
    int* coff  = cnt + 32;           // 33 entries
    int* fill  = coff + 33;
    int* elist = fill + 32;

    const int g = blockIdx.x;
    const int tid = threadIdx.x;

    // ---- init degree counters ----
    if (tid < 32) { cnt[tid] = 0; fill[tid] = 0; }
    __syncthreads();

    // ---- load edges (local node ids) + degree count (threads 0..255) ----
    int myT = -1;
    if (tid < 256) {
        int s = src[g*EPG + tid] - g*NPG;
        int t = dst[g*EPG + tid] - g*NPG;
        esrc[tid] = s;
        edst[tid] = t;
        myT = t;
        atomicAdd(&cnt[t], 1);
    }
    // ---- load x transposed into agg region: xT[k][n] ----
    for (int i = tid; i < NPG*INDIM; i += NTHREADS) {
        int n = i >> 7, k = i & 127;
        agg[k*32 + n] = x[(g*NPG + n)*INDIM + k];
    }
    if (tid < 256) avec[tid] = a1[tid];
    __syncthreads();

    // ---- CSR prefix + scatter ----
    if (tid == 0) {
        int s = 0;
        for (int i = 0; i < 32; i++) { coff[i] = s; s += cnt[i]; }
        coff[32] = s;
    }
    __syncthreads();
    if (tid < 256) {
        int pos = coff[myT] + atomicAdd(&fill[myT], 1);
        elist[pos] = tid;
    }

    // ---- layer 1 GEMM ----
    gemm_dual<INDIM>(W1s, b1s, W1d, b1d, agg, hs, hd, tid);
    __syncthreads();

    // ---- layer 1 attention ----
    attention_block(hs, hd, avec, elog, invd, agg, esrc, edst, cnt, coff, elist, tid);

    // ---- head maxpool -> hbuf as [64][32] (k-major) ----
    for (int i = tid; i < NPG*64; i += NTHREADS) {
        int n = i >> 6, d = i & 63;
        const float* ar = agg + n*HOUT + d;
        float m = fmaxf(fmaxf(ar[0], ar[64]), fmaxf(ar[128], ar[192]));
        hbuf[d*32 + n] = m;
    }
    if (tid < 256) avec[tid] = a2[tid];
    __syncthreads();

    // ---- layer 2 GEMM ----
    gemm_dual<64>(W2s, b2s, W2d, b2d, hbuf, hs, hd, tid);
    __syncthreads();

    // ---- layer 2 attention ----
    attention_block(hs, hd, avec, elog, invd, agg, esrc, edst, cnt, coff, elist, tid);

    // ---- head maxpool -> hbuf as [32][64] row-major ----
    for (int i = tid; i < NPG*64; i += NTHREADS) {
        int n = i >> 6, d = i & 63;
        const float* ar = agg + n*HOUT + d;
        float m = fmaxf(fmaxf(ar[0], ar[64]), fmaxf(ar[128], ar[192]));
        hbuf[n*64 + d] = m;
    }
    __syncthreads();

    // ---- global attention pooling ----
    if (tid < 32) {
        int n = tid;
        float acc = __ldg(bg);
        const float* hr = hbuf + n*64;
#pragma unroll 8
        for (int d = 0; d < 64; d++) acc = fmaf(hr[d], __ldg(Wg + d), acc);
        float m = acc;
#pragma unroll
        for (int off = 16; off > 0; off >>= 1)
            m = fmaxf(m, __shfl_xor_sync(0xffffffffu, m, off));
        float ex = expf(acc - m);
        float den = ex;
#pragma unroll
        for (int off = 16; off > 0; off >>= 1)
            den += __shfl_xor_sync(0xffffffffu, den, off);
        alphaS[n] = ex / den;
    }
    __syncthreads();
    if (tid < 64) {
        int d = tid;
        float o = 0.f;
#pragma unroll 8
        for (int n = 0; n < 32; n++) o = fmaf(alphaS[n], hbuf[n*64 + d], o);
        out[g*64 + d] = o;
    }
}

extern "C" void kernel_launch(void* const* d_in, const int* in_sizes, int n_in,
                              void* d_out, int out_size) {
    const float* x   = (const float*)d_in[0];
    const int*   src = (const int*)d_in[1];
    const int*   dst = (const int*)d_in[2];
    const float* W1s = (const float*)d_in[4];
    const float* b1s = (const float*)d_in[5];
    const float* W1d = (const float*)d_in[6];
    const float* b1d = (const float*)d_in[7];
    const float* a1  = (const float*)d_in[8];
    const float* W2s = (const float*)d_in[9];
    const float* b2s = (const float*)d_in[10];
    const float* W2d = (const float*)d_in[11];
    const float* b2d = (const float*)d_in[12];
    const float* a2  = (const float*)d_in[13];
    const float* Wg  = (const float*)d_in[14];
    const float* bg  = (const float*)d_in[15];
    float* out = (float*)d_out;

    cudaFuncSetAttribute(gat_fused_kernel,
                         cudaFuncAttributeMaxDynamicSharedMemorySize, SMEM_BYTES);
    gat_fused_kernel<<<NGRAPHS, NTHREADS, SMEM_BYTES>>>(
        x, src, dst, W1s, b1s, W1d, b1d, a1,
        W2s, b2s, W2d, b2d, a2, Wg, bg, out);
}

// round 4
// speedup vs baseline: 1.5492x; 1.3452x over previous
#include <cuda_runtime.h>
#include <math.h>

#define NGRAPHS 2048
#define NPG     32
#define EPG     256
#define INDIM   128
#define HOUT    256     // 4 heads * 64
#define HSR     258     // row stride for hs/hd: EVEN (float2-aligned), 258%32==2 -> 2-way worst
#define XSR     34      // row stride for k-major inputs (xT / hbuf)
#define ELS     5       // elog stride (scalar access; gcd(5,32)=1 conflict-free)
#define NTHREADS 512

__device__ __forceinline__ float2 ffma2(float2 a, float2 b, float2 c) {
    float2 d;
    asm("fma.rn.f32x2 %0, %1, %2, %3;"
        : "=l"(*(unsigned long long*)&d)
        : "l"(*(unsigned long long*)&a),
          "l"(*(unsigned long long*)&b),
          "l"(*(unsigned long long*)&c));
    return d;
}
__device__ __forceinline__ float2 fadd2(float2 a, float2 b) {
    float2 d;
    asm("add.rn.f32x2 %0, %1, %2;"
        : "=l"(*(unsigned long long*)&d)
        : "l"(*(unsigned long long*)&a),
          "l"(*(unsigned long long*)&b));
    return d;
}

#define SMEM_FLOATS (32*HSR*2 + 8192 + 64*XSR + 256 + 128 + 32)
#define SMEM_INTS   (256 + 256 + 32 + 33 + 32 + 256)
#define SMEM_BYTES  ((SMEM_FLOATS + SMEM_INTS) * 4)

// Dual GEMM, 512 threads. m=tid>>8 (s/d matrix), cg=(tid>>2)&63 (4 cols), ng=tid&3 (8 nodes).
template<int K>
__device__ __forceinline__ void gemm_dual(
    const float* __restrict__ Ws, const float* __restrict__ bsv,
    const float* __restrict__ Wd, const float* __restrict__ bdv,
    const float* xT, float* hs, float* hd, int tid)
{
    const int m  = tid >> 8;
    const int cg = (tid >> 2) & 63;
    const int ng = tid & 3;
    const float* W  = m ? Wd  : Ws;
    const float* bv = m ? bdv : bsv;
    float* out      = m ? hd  : hs;
    const int j0 = cg * 4;

    float2 acc[4][4];
#pragma unroll
    for (int c = 0; c < 4; c++) {
        float b = __ldg(bv + j0 + c);
#pragma unroll
        for (int i = 0; i < 4; i++) acc[c][i] = make_float2(b, b);
    }
    const float2* xbase = (const float2*)xT + ng * 4;
#pragma unroll 8
    for (int k = 0; k < K; k++) {
        float4 w = __ldg((const float4*)(W + k * HOUT) + cg);
        const float2* xr = xbase + k * (XSR/2);
        float2 x0 = xr[0], x1 = xr[1], x2 = xr[2], x3 = xr[3];
        float2 w0 = make_float2(w.x, w.x);
        float2 w1 = make_float2(w.y, w.y);
        float2 w2 = make_float2(w.z, w.z);
        float2 w3 = make_float2(w.w, w.w);
        acc[0][0] = ffma2(x0, w0, acc[0][0]);
        acc[0][1] = ffma2(x1, w0, acc[0][1]);
        acc[0][2] = ffma2(x2, w0, acc[0][2]);
        acc[0][3] = ffma2(x3, w0, acc[0][3]);
        acc[1][0] = ffma2(x0, w1, acc[1][0]);
        acc[1][1] = ffma2(x1, w1, acc[1][1]);
        acc[1][2] = ffma2(x2, w1, acc[1][2]);
        acc[1][3] = ffma2(x3, w1, acc[1][3]);
        acc[2][0] = ffma2(x0, w2, acc[2][0]);
        acc[2][1] = ffma2(x1, w2, acc[2][1]);
        acc[2][2] = ffma2(x2, w2, acc[2][2]);
        acc[2][3] = ffma2(x3, w2, acc[2][3]);
        acc[3][0] = ffma2(x0, w3, acc[3][0]);
        acc[3][1] = ffma2(x1, w3, acc[3][1]);
        acc[3][2] = ffma2(x2, w3, acc[3][2]);
        acc[3][3] = ffma2(x3, w3, acc[3][3]);
    }
#pragma unroll
    for (int c = 0; c < 4; c++)
#pragma unroll
        for (int i = 0; i < 4; i++) {
            out[(ng*8 + 2*i)  * HSR + j0 + c] = acc[c][i].x;
            out[(ng*8 + 2*i+1)* HSR + j0 + c] = acc[c][i].y;
        }
}

// logits -> per-(dst,head) softmax (CSR) -> aggregation
__device__ __forceinline__ void attention_block(
    const float* hs, const float* hd, const float* avec,
    float* elog, float* invd, float* agg,
    const int* esrc, const int* edst, const int* cnt, const int* coff,
    const int* elist, int tid)
{
    // ---- edge logits: 256 edges x 2 head-pairs ----
    {
        int e  = tid & 255;
        int hp = tid >> 8;
        int s = esrc[e], t = edst[e];
        const float2* ps = (const float2*)(hs + s * HSR);
        const float2* pd = (const float2*)(hd + t * HSR);
        const float2* pa = (const float2*)avec;
#pragma unroll
        for (int hh = 0; hh < 2; hh++) {
            int h = 2*hp + hh;
            float f1x = 0.f, f1y = 0.f, f2x = 0.f, f2y = 0.f;
#pragma unroll 8
            for (int d2 = 0; d2 < 32; d2++) {
                float2 vs = ps[h*32 + d2];
                float2 vd = pd[h*32 + d2];
                float2 av = pa[h*32 + d2];
                float2 v  = fadd2(vs, vd);
                f1x = fmaf(av.x, v.x, f1x);
                f1y = fmaf(av.y, v.y, f1y);
                f2x = fmaf(av.x, fabsf(v.x), f2x);
                f2y = fmaf(av.y, fabsf(v.y), f2y);
            }
            // leaky_relu(v) = 0.6v + 0.4|v|  (slope 0.2)
            elog[e*ELS + h] = 0.6f*(f1x + f1y) + 0.4f*(f2x + f2y);
        }
    }
    __syncthreads();

    // ---- softmax per (dst node, head): 128 workers ----
    if (tid < 128) {
        int n = tid >> 2, h = tid & 3;
        int b = coff[n], c = cnt[n];
        float m = -1e30f;
        for (int i = 0; i < c; i++) m = fmaxf(m, elog[elist[b+i]*ELS + h]);
        float den = 0.f;
        for (int i = 0; i < c; i++) {
            int e = elist[b+i];
            float ex = __expf(elog[e*ELS + h] - m);
            elog[e*ELS + h] = ex;
            den += ex;
        }
        invd[tid] = c ? (1.f / den) : 0.f;
    }
    __syncthreads();

    // ---- aggregation: 32 nodes x 16 threads, 16 dims each, rotated chunk order ----
    {
        int n = tid >> 4, dg = tid & 15, h = dg >> 2;
        int b = coff[n], c = cnt[n];
        float iv = invd[n*4 + h];
        int r = dg >> 1;
        int idx[8];
#pragma unroll
        for (int f = 0; f < 8; f++) idx[f] = (f + r) & 7;
        float2 acc[8];
#pragma unroll
        for (int f = 0; f < 8; f++) acc[f] = make_float2(0.f, 0.f);
        for (int i = 0; i < c; i++) {
            int e  = elist[b+i];
            int s2 = esrc[e];
            float al = elog[e*ELS + h] * iv;
            float2 a2 = make_float2(al, al);
            const float2* pr = (const float2*)(hs + s2*HSR + dg*16);
#pragma unroll
            for (int f = 0; f < 8; f++) acc[f] = ffma2(pr[idx[f]], a2, acc[f]);
        }
        float2* po = (float2*)(agg + n*HOUT + dg*16);
#pragma unroll
        for (int f = 0; f < 8; f++) po[idx[f]] = acc[f];
    }
    __syncthreads();
}

__global__ void __launch_bounds__(NTHREADS)
gat_fused_kernel(const float* __restrict__ x,
                 const int* __restrict__ src, const int* __restrict__ dst,
                 const float* __restrict__ W1s, const float* __restrict__ b1s,
                 const float* __restrict__ W1d, const float* __restrict__ b1d,
                 const float* __restrict__ a1,
                 const float* __restrict__ W2s, const float* __restrict__ b2s,
                 const float* __restrict__ W2d, const float* __restrict__ b2d,
                 const float* __restrict__ a2,
                 const float* __restrict__ Wg, const float* __restrict__ bg,
                 float* __restrict__ out)
{
    extern __shared__ float smem[];
    float* hs     = smem;
    float* hd     = hs + 32*HSR;
    float* agg    = hd + 32*HSR;     // 8192 floats (also xT, stride 34, for layer-1 GEMM)
    float* hbuf   = agg + 8192;      // 64*34 = 2176 floats; elog aliases first 1280
    float* elog   = hbuf;
    float* avec   = hbuf + 64*XSR;   // 256
    float* invd   = avec + 256;      // 128
    float* alphaS = invd + 128;      // 32
    int* esrc  = (int*)(alphaS + 32);
    int* edst  = esrc + EPG;
    int* cnt   = edst + EPG;
    int* coff  = cnt + 32;
    int* fill  = coff + 33;
    int* elist = fill + 32;

    const int g = blockIdx.x;
    const int tid = threadIdx.x;

    if (tid < 32) { cnt[tid] = 0; fill[tid] = 0; }
    __syncthreads();

    int myT = -1;
    if (tid < 256) {
        int s = src[g*EPG + tid] - g*NPG;
        int t = dst[g*EPG + tid] - g*NPG;
        esrc[tid] = s;
        edst[tid] = t;
        myT = t;
        atomicAdd(&cnt[t], 1);
    }
    // x -> xT[k*34 + n]
    for (int i = tid; i < NPG*INDIM; i += NTHREADS) {
        int n = i >> 7, k = i & 127;
        agg[k*XSR + n] = x[(g*NPG + n)*INDIM + k];
    }
    if (tid < 256) avec[tid] = a1[tid];
    __syncthreads();

    if (tid == 0) {
        int s = 0;
        for (int i = 0; i < 32; i++) { coff[i] = s; s += cnt[i]; }
        coff[32] = s;
    }
    __syncthreads();
    if (tid < 256) {
        int pos = coff[myT] + atomicAdd(&fill[myT], 1);
        elist[pos] = tid;
    }

    // ---- layer 1 ----
    gemm_dual<INDIM>(W1s, b1s, W1d, b1d, agg, hs, hd, tid);
    __syncthreads();
    attention_block(hs, hd, avec, elog, invd, agg, esrc, edst, cnt, coff, elist, tid);

    // head maxpool -> hbuf[d*34 + n] (k-major for layer-2 GEMM)
    for (int i = tid; i < NPG*64; i += NTHREADS) {
        int n = i >> 6, d = i & 63;
        const float* ar = agg + n*HOUT + d;
        float m = fmaxf(fmaxf(ar[0], ar[64]), fmaxf(ar[128], ar[192]));
        hbuf[d*XSR + n] = m;
    }
    if (tid < 256) avec[tid] = a2[tid];
    __syncthreads();

    // ---- layer 2 ----
    gemm_dual<64>(W2s, b2s, W2d, b2d, hbuf, hs, hd, tid);
    __syncthreads();
    attention_block(hs, hd, avec, elog, invd, agg, esrc, edst, cnt, coff, elist, tid);

    // head maxpool -> hbuf[n*64 + d] row-major
    for (int i = tid; i < NPG*64; i += NTHREADS) {
        int n = i >> 6, d = i & 63;
        const float* ar = agg + n*HOUT + d;
        float m = fmaxf(fmaxf(ar[0], ar[64]), fmaxf(ar[128], ar[192]));
        hbuf[n*64 + d] = m;
    }
    __syncthreads();

    // ---- global attention pooling ----
    if (tid < 32) {
        int n = tid;
        float acc = __ldg(bg);
        const float* hr = hbuf + n*64;
#pragma unroll 8
        for (int d = 0; d < 64; d++) acc = fmaf(hr[d], __ldg(Wg + d), acc);
        float m = acc;
#pragma unroll
        for (int off = 16; off > 0; off >>= 1)
            m = fmaxf(m, __shfl_xor_sync(0xffffffffu, m, off));
        float ex = __expf(acc - m);
        float den = ex;
#pragma unroll
        for (int off = 16; off > 0; off >>= 1)
            den += __shfl_xor_sync(0xffffffffu, den, off);
        alphaS[n] = ex / den;
    }
    __syncthreads();
    if (tid < 64) {
        int d = tid;
        float o = 0.f;
#pragma unroll 8
        for (int n = 0; n < 32; n++) o = fmaf(alphaS[n], hbuf[n*64 + d], o);
        out[g*64 + d] = o;
    }
}

extern "C" void kernel_launch(void* const* d_in, const int* in_sizes, int n_in,
                              void* d_out, int out_size) {
    const float* x   = (const float*)d_in[0];
    const int*   src = (const int*)d_in[1];
    const int*   dst = (const int*)d_in[2];
    const float* W1s = (const float*)d_in[4];
    const float* b1s = (const float*)d_in[5];
    const float* W1d = (const float*)d_in[6];
    const float* b1d = (const float*)d_in[7];
    const float* a1  = (const float*)d_in[8];
    const float* W2s = (const float*)d_in[9];
    const float* b2s = (const float*)d_in[10];
    const float* W2d = (const float*)d_in[11];
    const float* b2d = (const float*)d_in[12];
    const float* a2  = (const float*)d_in[13];
    const float* Wg  = (const float*)d_in[14];
    const float* bg  = (const float*)d_in[15];
    float* out = (float*)d_out;

    cudaFuncSetAttribute(gat_fused_kernel,
                         cudaFuncAttributeMaxDynamicSharedMemorySize, SMEM_BYTES);
    gat_fused_kernel<<<NGRAPHS, NTHREADS, SMEM_BYTES>>>(
        x, src, dst, W1s, b1s, W1d, b1d, a1,
        W2s, b2s, W2d, b2d, a2, Wg, bg, out);
}